// round 4
// baseline (speedup 1.0000x reference)
#include <cuda_runtime.h>

// Problem constants (fixed by the reference setup)
#define LSEQ   768
#define BATCH  2
#define N_MSA  4
#define DM     128
#define NREL   63                        // 2*MAX_LEN - 1
#define NSM    148
#define GRID   (NSM * 8)                 // 1184 blocks, one full wave
#define NWARPS (GRID * 8)                // 9472 global warps
#define TOTALROWS (BATCH * LSEQ * LSEQ)  // 1,179,648 rows of 128 floats

// Scratch tables (device globals — no allocation allowed)
__device__ float g_Ptab[5][DM];   // masked_emb[t] @ W_proj[:64, :]
__device__ float g_Qtab[5][DM];   // masked_emb[t] @ W_proj[64:, :]
__device__ float g_R[NREL][DM];   // W_pos[r] + b_proj + b_pos

// ---------------------------------------------------------------------------
// Table setup: 68 tiny blocks. Blocks 0..4 -> Ptab/Qtab row t,
// blocks 5..67 -> R row (blockIdx-5).
// ---------------------------------------------------------------------------
__global__ void setup_kernel(const float* __restrict__ emb,
                             const float* __restrict__ W_proj,
                             const float* __restrict__ b_proj,
                             const float* __restrict__ W_pos,
                             const float* __restrict__ b_pos) {
    int d = threadIdx.x;          // 0..127
    int task = blockIdx.x;
    if (task < 5) {
        int t = task;
        float pt = 0.f, qt = 0.f;
        if (t != 0) {             // token 0 is masked to zero
            #pragma unroll 16
            for (int k = 0; k < 64; k++) {
                float ek = emb[t * 64 + k];
                pt = fmaf(ek, W_proj[k * DM + d], pt);
                qt = fmaf(ek, W_proj[(64 + k) * DM + d], qt);
            }
        }
        g_Ptab[t][d] = pt;
        g_Qtab[t][d] = qt;
    } else {
        int r = task - 5;
        g_R[r][d] = W_pos[r * DM + d] + b_proj[d] + b_pos[d];
    }
}

// ---------------------------------------------------------------------------
// Main kernel: warp-level grid-stride over flat output rows r = (b,i,j).
// All 9472 warps sweep ONE contiguous ~4.8MB frontier through the 604MB
// output (memset-like address stream -> DRAM row-buffer locality).
// Per row: v = P[seq[i]] + Q[seq[j]] + R[clip(i-j)], with the two saturated
// R rows (92% of rows) kept in registers, mid rows read from L2.
// ---------------------------------------------------------------------------
__global__ __launch_bounds__(256, 8) void pair_kernel(const int* __restrict__ msa,
                                                      float* __restrict__ out) {
    __shared__ unsigned char s_seq[BATCH * LSEQ];  // token ids (0..4) as bytes
    __shared__ float4 s_P[5 * 32];
    __shared__ float4 s_Q[5 * 32];

    int tid  = threadIdx.x;
    int lane = tid & 31;
    int warp = tid >> 5;

    // Load both batches' sequences (row 0 of each MSA) as bytes
    for (int k = tid; k < BATCH * LSEQ; k += 256) {
        int b   = (k >= LSEQ);
        int idx = b ? (N_MSA * LSEQ + (k - LSEQ)) : k;
        s_seq[k] = (unsigned char)msa[idx];
    }
    if (tid < 5 * 32) {
        s_P[tid] = ((const float4*)g_Ptab)[tid];
        s_Q[tid] = ((const float4*)g_Qtab)[tid];
    }
    __syncthreads();

    // Saturated R rows live in registers (one float4 per lane)
    const float4* gR4 = (const float4*)g_R;
    float4 rHI = gR4[ 0 * 32 + lane];   // rel = 0   (j >= i+31)
    float4 rLO = gR4[62 * 32 + lane];   // rel = 62  (j <= i-31)

    float4* out4 = (float4*)out;
    int gw = blockIdx.x * 8 + warp;

    for (int r = gw; r < TOTALROWS; r += NWARPS) {
        int bi = r / LSEQ;                 // b*LSEQ + i   (0..1535)
        int j  = r - bi * LSEQ;
        int bo = (bi >= LSEQ) ? LSEQ : 0;  // batch offset into s_seq
        int i  = bi - bo;

        int si = s_seq[bi];                // warp-uniform
        int sj = s_seq[bo + j];            // warp-uniform

        float4 p = s_P[si * 32 + lane];
        float4 q = s_Q[sj * 32 + lane];

        int dd = i - j;
        float4 rr;
        if (dd >= 31) {                    // warp-uniform branches
            rr = rLO;
        } else if (dd <= -31) {
            rr = rHI;
        } else {
            rr = __ldg(&gR4[(dd + 31) * 32 + lane]);
        }

        float4 v = make_float4(p.x + q.x + rr.x,
                               p.y + q.y + rr.y,
                               p.z + q.z + rr.z,
                               p.w + q.w + rr.w);
        __stcs(&out4[(size_t)r * 32 + lane], v);
    }
}

extern "C" void kernel_launch(void* const* d_in, const int* in_sizes, int n_in,
                              void* d_out, int out_size) {
    const int*   msa    = (const int*)  d_in[0];  // msa_tokens (B, N_MSA, L) int32
    const float* emb    = (const float*)d_in[1];  // (5, 64)
    const float* W_proj = (const float*)d_in[2];  // (128, 128)
    const float* b_proj = (const float*)d_in[3];  // (128,)
    const float* W_pos  = (const float*)d_in[4];  // (63, 128)
    const float* b_pos  = (const float*)d_in[5];  // (128,)
    float* out = (float*)d_out;                   // (B, L, L, 128) fp32

    setup_kernel<<<5 + NREL, DM>>>(emb, W_proj, b_proj, W_pos, b_pos);
    pair_kernel<<<GRID, 256>>>(msa, out);
}